// round 16
// baseline (speedup 1.0000x reference)
#include <cuda_runtime.h>
#include <cuda_fp16.h>

// ---------------------------------------------------------------------------
// Inverse DTCWT, 3 levels. Split kernels, fp16 intermediates, interleaved
// padded y buffer. R16: kA n-QUAD (two-pass), kC m-QUAD, kB/kD 2-rows.
// ---------------------------------------------------------------------------

#define SH   0.70710678118654752440f
#define C_A  0.23389032f
#define C_B  0.5875183f
#define C_C  0.11430184f
#define C_D  0.76027237f
#define C_E  0.08832942f
#define C_F  0.03516384f

#define G0   0.35355339059327f
#define G1   0.70710678118655f
#define Q_E  (-0.08838834764832f)
#define Q_D  (-0.17677669529664f)
#define Q_F  0.53033008588991f

#define LP0(L) ( C_A*L[1] + C_B*L[2] - C_C*L[3])
#define LP1(L) ( C_D*L[5] - C_E*L[6] + C_F*L[7])
#define LP2(L) ( C_F*L[0] - C_E*L[1] + C_D*L[2])
#define LP3(L) (-C_C*L[4] + C_B*L[5] + C_A*L[6])
#define HP0(H) (-C_D*H[5] + C_E*H[6] - C_F*H[7])
#define HP1(H) ( C_A*H[1] + C_B*H[2] - C_C*H[3])
#define HP2(H) (-C_C*H[4] + C_B*H[5] + C_A*H[6])
#define HP3(H) (-C_F*H[0] + C_E*H[1] - C_D*H[2])

__device__ uint2  g_yp[128 * 256 * 134];
__device__ __half g_z128[128 * 128 * 128];
__device__ __half g_z256[128 * 256 * 256];

__device__ __forceinline__ int refl(int i, int n) {
    i = (i < 0) ? (-1 - i) : i;
    return (i >= n) ? (2 * n - 1 - i) : i;
}

__host__ __device__ constexpr int ilog2c(int v) { return v <= 1 ? 0 : 1 + ilog2c(v >> 1); }

__device__ __forceinline__ float  ld1(const float* p)   { return __ldg(p); }
__device__ __forceinline__ float  ld1(const __half* p)  { return __half2float(__ldg(p)); }
__device__ __forceinline__ float2 ld2(const float2* p)  { return __ldg(p); }
__device__ __forceinline__ float2 ld2(const __half2* p) { return __half22float2(__ldg(p)); }

__device__ __forceinline__ uint2 pack2(__half2 a, __half2 b) {
    uint2 r;
    r.x = *reinterpret_cast<const unsigned*>(&a);
    r.y = *reinterpret_cast<const unsigned*>(&b);
    return r;
}
__device__ __forceinline__ float2 unpk_lo(uint2 v) {
    __half2 h = *reinterpret_cast<const __half2*>(&v.x);
    return __half22float2(h);
}
__device__ __forceinline__ float2 unpk_hi(uint2 v) {
    __half2 h = *reinterpret_cast<const __half2*>(&v.y);
    return __half22float2(h);
}

template <typename T> struct vec2of;
template <> struct vec2of<float>  { using t = float2; };
template <> struct vec2of<__half> { using t = __half2; };

// ===========================================================================
// kA scalar path (single n, single col).
// ===========================================================================
template <int RI, int CI, typename TZ>
__device__ void kA_scalar(const TZ* __restrict__ z, const float* __restrict__ yh,
                          uint2* __restrict__ yp, int b, int n, int jc, int pc) {
    constexpr int rh = RI / 2, PS2 = (CI + 12) / 2;
    const int d8[8] = {-4, -2, 0, 2, -1, 1, 3, 5};
    int pj = jc & 1;
    int rw[8], oB[8];
    float s1v[8], s2v[8];
#pragma unroll
    for (int t = 0; t < 8; t++) {
        int rr = refl(2 * n + d8[t], RI);
        rw[t] = rr;
        int ii = rr >> 1, pi = rr & 1;
        oB[t] = ii * CI + (pi ^ pj);
        s1v[t] = (pi & pj) ? -1.f : 1.f;
        s2v[t] = (pi & (pj ^ 1)) ? -1.f : 1.f;
    }
    const TZ* zb = z + (size_t)b * RI * CI + jc;
    const float* yb = yh + (size_t)b * 6 * rh * CI + 2 * (jc >> 1);
    const int sb = rh * CI;

    float L[8], H[8], A[8], B[8];
#pragma unroll
    for (int t = 0; t < 8; t++) L[t] = ld1(zb + rw[t] * CI);
#pragma unroll
    for (int t = 0; t < 8; t++) {
        H[t] = s1v[t] * __ldg(yb + oB[t]) + s2v[t] * __ldg(yb + 5 * sb + oB[t]);
        A[t] = s1v[t] * __ldg(yb + 2 * sb + oB[t]) + s2v[t] * __ldg(yb + 3 * sb + oB[t]);
        B[t] = s1v[t] * __ldg(yb + 1 * sb + oB[t]) + s2v[t] * __ldg(yb + 4 * sb + oB[t]);
    }

    __half* o = (__half*)yp + (((size_t)b * 2 * RI + 4 * n) * PS2 + (pc >> 1)) * 4 + (pc & 1);
    const int rs = PS2 * 4;
    o[0]          = __float2half(LP0(L) + SH * HP0(H));
    o[2]          = __float2half(SH * (LP0(A) + HP0(B)));
    o[rs]         = __float2half(LP1(L) + SH * HP1(H));
    o[rs + 2]     = __float2half(SH * (LP1(A) + HP1(B)));
    o[2 * rs]     = __float2half(LP2(L) + SH * HP2(H));
    o[2 * rs + 2] = __float2half(SH * (LP2(A) + HP2(B)));
    o[3 * rs]     = __float2half(LP3(L) + SH * HP3(H));
    o[3 * rs + 2] = __float2half(SH * (LP3(A) + HP3(B)));
}

// ===========================================================================
// kA: column upsampling, n-QUAD per thread (n0..n0+3 -> 16 output rows x 2).
// Subband rows n0-2..n0+5 (8) -> E[0..6] (w[t]), O[0..6] (w[t+1]).
// z evens 2n0-4..2n0+8 (ze[7]), odds 2n0-1..2n0+11 (zo[7]).
// Output n0+r uses slice [r..r+3] of each window array.
// ===========================================================================
template <int RI, int CI, typename TZ>
__global__ void __launch_bounds__(256)
kA(const TZ* __restrict__ z, const float* __restrict__ yh,
   uint2* __restrict__ yp) {
    constexpr int rh = RI / 2, ch = CI / 2, JP = ch + 5, PS2 = (CI + 12) / 2;
    constexpr int NQ = rh / 4;
    using TZ2 = typename vec2of<TZ>::t;
    unsigned idx = blockIdx.x * 256u + threadIdx.x;
    int jp = idx % JP;
    int nq = (idx / JP) % NQ;
    int b = idx / (JP * NQ);
    int n = 4 * nq;

    if (jp < ch && nq >= 1 && nq <= NQ - 2) {
        const TZ2* z2 = (const TZ2*)z + (size_t)b * RI * ch + jp;
        const float2* yb2 = (const float2*)yh + (size_t)b * 6 * rh * ch + jp;
        const int sstr = rh * ch;
        int base = 2 * n;

#define LOAD_PAIR8(S1, S2, E0, E1, O0, O1)                                    \
    {                                                                         \
        float2 w1[8], w2[8];                                                  \
        _Pragma("unroll") for (int t = 0; t < 8; t++) {                       \
            w1[t] = __ldg(yb2 + ((S1) * sstr + (n - 2 + t) * ch));            \
            w2[t] = __ldg(yb2 + ((S2) * sstr + (n - 2 + t) * ch));            \
        }                                                                     \
        _Pragma("unroll") for (int t = 0; t < 7; t++) {                       \
            E0[t] = w1[t].x + w2[t].x;                                        \
            E1[t] = w1[t].y + w2[t].y;                                        \
            O0[t] = w1[t + 1].y - w2[t + 1].y;                                \
            O1[t] = w2[t + 1].x - w1[t + 1].x;                                \
        }                                                                     \
    }

        __half2 y1h[16];
        // ---------- pass 1: y1 = ifilt_lp(z) + SH * ifilt_hp(lh) ----------
        {
            float2 ze[7], zo[7];
#pragma unroll
            for (int t = 0; t < 7; t++) {
                ze[t] = ld2(z2 + (base - 4 + 2 * t) * ch);
                zo[t] = ld2(z2 + (base - 1 + 2 * t) * ch);
            }
            float E0[7], E1[7], O0[7], O1[7];
            LOAD_PAIR8(0, 5, E0, E1, O0, O1);
#pragma unroll
            for (int r = 0; r < 4; r++) {
                float L0[8], L1[8], H0[8], H1[8];
#pragma unroll
                for (int t = 0; t < 4; t++) {
                    L0[t] = ze[r + t].x; L1[t] = ze[r + t].y;
                    L0[4 + t] = zo[r + t].x; L1[4 + t] = zo[r + t].y;
                    H0[t] = E0[r + t]; H1[t] = E1[r + t];
                    H0[4 + t] = O0[r + t]; H1[4 + t] = O1[r + t];
                }
                y1h[4 * r + 0] = __floats2half2_rn(LP0(L0) + SH * HP0(H0), LP0(L1) + SH * HP0(H1));
                y1h[4 * r + 1] = __floats2half2_rn(LP1(L0) + SH * HP1(H0), LP1(L1) + SH * HP1(H1));
                y1h[4 * r + 2] = __floats2half2_rn(LP2(L0) + SH * HP2(H0), LP2(L1) + SH * HP2(H1));
                y1h[4 * r + 3] = __floats2half2_rn(LP3(L0) + SH * HP3(H0), LP3(L1) + SH * HP3(H1));
            }
        }
        // ---------- pass 2: y2 = SH * (ifilt_lp(hl) + ifilt_hp(hh)) ----------
        {
            float AE0[7], AE1[7], AO0[7], AO1[7];
            float BE0[7], BE1[7], BO0[7], BO1[7];
            LOAD_PAIR8(2, 3, AE0, AE1, AO0, AO1);  // hl
            LOAD_PAIR8(1, 4, BE0, BE1, BO0, BO1);  // hh
            uint2* o = yp + ((size_t)b * 2 * RI + 4 * n) * PS2 + (jp + 2);
#pragma unroll
            for (int r = 0; r < 4; r++) {
                float A0[8], A1[8], B0[8], B1[8];
#pragma unroll
                for (int t = 0; t < 4; t++) {
                    A0[t] = AE0[r + t]; A1[t] = AE1[r + t];
                    A0[4 + t] = AO0[r + t]; A1[4 + t] = AO1[r + t];
                    B0[t] = BE0[r + t]; B1[t] = BE1[r + t];
                    B0[4 + t] = BO0[r + t]; B1[4 + t] = BO1[r + t];
                }
                __half2 h0 = __floats2half2_rn(SH * (LP0(A0) + HP0(B0)), SH * (LP0(A1) + HP0(B1)));
                __half2 h1 = __floats2half2_rn(SH * (LP1(A0) + HP1(B0)), SH * (LP1(A1) + HP1(B1)));
                __half2 h2 = __floats2half2_rn(SH * (LP2(A0) + HP2(B0)), SH * (LP2(A1) + HP2(B1)));
                __half2 h3 = __floats2half2_rn(SH * (LP3(A0) + HP3(B0)), SH * (LP3(A1) + HP3(B1)));
                o[(4 * r + 0) * PS2] = pack2(y1h[4 * r + 0], h0);
                o[(4 * r + 1) * PS2] = pack2(y1h[4 * r + 1], h1);
                o[(4 * r + 2) * PS2] = pack2(y1h[4 * r + 2], h2);
                o[(4 * r + 3) * PS2] = pack2(y1h[4 * r + 3], h3);
            }
        }
#undef LOAD_PAIR8
    } else if (jp < ch) {
#pragma unroll
        for (int dn = 0; dn < 4; dn++) {
            kA_scalar<RI, CI, TZ>(z, yh, yp, b, n + dn, 2 * jp, 2 * jp + 4);
            kA_scalar<RI, CI, TZ>(z, yh, yp, b, n + dn, 2 * jp + 1, 2 * jp + 5);
        }
    } else {
        int hp = jp - ch;
        int pc0 = (hp < 2) ? 2 * hp : (CI + 2 * hp);
#pragma unroll
        for (int dn = 0; dn < 4; dn++) {
#pragma unroll
            for (int s = 0; s < 2; s++) {
                int pc = pc0 + s;
                int jc = refl(pc - 4, CI);
                kA_scalar<RI, CI, TZ>(z, yh, yp, b, n + dn, jc, pc);
            }
        }
    }
}

// ===========================================================================
// kB: branch-free row upsampling, 2 rows per thread.
// ===========================================================================
template <int RO, int CO>
__global__ void __launch_bounds__(256)
kB(const uint2* __restrict__ yp, __half* __restrict__ Z) {
    constexpr int ch = CO / 4;
    constexpr int PS2 = (CO / 2 + 12) / 2;
    constexpr int LCH = ilog2c(ch);
    unsigned idx = blockIdx.x * 256u + threadIdx.x;
    int n = idx & (ch - 1);
    int rp = idx >> LCH;
    int row0 = 2 * rp;

#pragma unroll
    for (int rr = 0; rr < 2; rr++) {
        int row = row0 + rr;
        const uint2* q = yp + (size_t)row * PS2 + n;
        uint2 v0 = __ldg(q), v1 = __ldg(q + 1), v2 = __ldg(q + 2),
              v3 = __ldg(q + 3), v4 = __ldg(q + 4);
        float2 u0 = unpk_lo(v0), u1 = unpk_lo(v1), u2 = unpk_lo(v2),
               u3 = unpk_lo(v3), u4 = unpk_lo(v4);
        float2 w0 = unpk_hi(v0), w1 = unpk_hi(v1), w2 = unpk_hi(v2),
               w3 = unpk_hi(v3), w4 = unpk_hi(v4);
        float L[8], H[8];
        L[0] = u0.x; L[1] = u1.x; L[2] = u2.x; L[3] = u3.x;
        L[4] = u1.y; L[5] = u2.y; L[6] = u3.y; L[7] = u4.y;
        H[0] = w0.x; H[1] = w1.x; H[2] = w2.x; H[3] = w3.x;
        H[4] = w1.y; H[5] = w2.y; H[6] = w3.y; H[7] = w4.y;

        __half2 ha = __floats2half2_rn(LP0(L) + HP0(H), LP1(L) + HP1(H));
        __half2 hb = __floats2half2_rn(LP2(L) + HP2(H), LP3(L) + HP3(H));
        reinterpret_cast<uint2*>(Z + (size_t)row * CO)[n] = pack2(ha, hb);
    }
}

// ===========================================================================
// kC scalar path (single m).
// ===========================================================================
template <int RI, int CI>
__device__ void kC_scalar(const __half* __restrict__ z, const float* __restrict__ yh,
                          uint2* __restrict__ yp, int b, int m, int jc, int pc) {
    constexpr int rh = RI / 2, PS2 = (CI + 10) / 2;
    int i0 = 2 * m;
    int pj = jc & 1;
    int o6[6];
    float s1v[6], s2v[6];
    int rr[6];
#pragma unroll
    for (int t = 0; t < 6; t++) {
        int rx = refl(i0 - 2 + t, RI);
        rr[t] = rx;
        int ii = rx >> 1, pi = rx & 1;
        o6[t] = ii * CI + (pi ^ pj);
        s1v[t] = (pi & pj) ? -1.f : 1.f;
        s2v[t] = (pi & (pj ^ 1)) ? -1.f : 1.f;
    }
    const __half* zb = z + (size_t)b * RI * CI + jc;
    const float* yb = yh + (size_t)b * 6 * rh * CI + 2 * (jc >> 1);
    const int sb = rh * CI;

    float zr[4];
#pragma unroll
    for (int t = 0; t < 4; t++) zr[t] = ld1(zb + rr[t + 1] * CI);

    float lr[6], hlr[6], hhr[6];
#pragma unroll
    for (int t = 0; t < 6; t++) {
        lr[t]  = s1v[t] * __ldg(yb + o6[t])          + s2v[t] * __ldg(yb + 5 * sb + o6[t]);
        hlr[t] = s1v[t] * __ldg(yb + 2 * sb + o6[t]) + s2v[t] * __ldg(yb + 3 * sb + o6[t]);
        hhr[t] = s1v[t] * __ldg(yb + 1 * sb + o6[t]) + s2v[t] * __ldg(yb + 4 * sb + o6[t]);
    }
    __half* o = (__half*)yp + (((size_t)b * RI + i0) * PS2 + (pc >> 1)) * 4 + (pc & 1);
    const int rs = PS2 * 4;
    o[0]      = __float2half(G0 * (zr[0] + zr[2]) + G1 * zr[1]
              + SH * (Q_E * (lr[0] + lr[4]) + Q_D * (lr[1] + lr[3]) + Q_F * lr[2]));
    o[rs]     = __float2half(G0 * (zr[1] + zr[3]) + G1 * zr[2]
              + SH * (Q_E * (lr[1] + lr[5]) + Q_D * (lr[2] + lr[4]) + Q_F * lr[3]));
    o[2]      = __float2half(SH * (G0 * (hlr[1] + hlr[3]) + G1 * hlr[2]
              + Q_E * (hhr[0] + hhr[4]) + Q_D * (hhr[1] + hhr[3]) + Q_F * hhr[2]));
    o[rs + 2] = __float2half(SH * (G0 * (hlr[2] + hlr[4]) + G1 * hlr[3]
              + Q_E * (hhr[1] + hhr[5]) + Q_D * (hhr[2] + hhr[4]) + Q_F * hhr[3]));
}

// ===========================================================================
// kC: final-level column filters, m-QUAD per thread, two-pass (R15 verbatim).
// ===========================================================================
template <int RI, int CI>
__global__ void __launch_bounds__(256)
kC(const __half* __restrict__ z, const float* __restrict__ yh,
   uint2* __restrict__ yp) {
    constexpr int rh = RI / 2, chb = CI / 2, JP = chb + 5, PS2 = (CI + 10) / 2;
    constexpr int MQ = rh / 4;
    unsigned idx = blockIdx.x * 256u + threadIdx.x;
    int jp = idx % JP;
    int mq = (idx / JP) % MQ;
    int b = idx / (JP * MQ);
    int mm = 4 * mq;
    int i0 = 2 * mm;

    if (jp < chb && mq >= 1 && mq <= MQ - 2) {
        const __half2* z2 = (const __half2*)z + (size_t)b * RI * chb + jp;
        const float2* yb2 = (const float2*)yh + (size_t)b * 6 * rh * chb + jp;
        const int sstr = rh * chb;

#define LOAD_PAIR6(S1, S2, B0, B1)                                            \
    {                                                                         \
        float2 w1[6], w2[6];                                                  \
        _Pragma("unroll") for (int t = 0; t < 6; t++) {                       \
            w1[t] = __ldg(yb2 + ((S1) * sstr + (mm - 1 + t) * chb));          \
            w2[t] = __ldg(yb2 + ((S2) * sstr + (mm - 1 + t) * chb));          \
        }                                                                     \
        _Pragma("unroll") for (int t = 0; t < 6; t++) {                       \
            B0[2 * t] = w1[t].x + w2[t].x;                                    \
            B1[2 * t] = w1[t].y + w2[t].y;                                    \
            B0[2 * t + 1] = w1[t].y - w2[t].y;                                \
            B1[2 * t + 1] = w2[t].x - w1[t].x;                                \
        }                                                                     \
    }

        __half2 y1h[8];
        {
            float2 zr[10];
#pragma unroll
            for (int t = 0; t < 10; t++) zr[t] = ld2(z2 + (i0 - 1 + t) * chb);
            float lr0[12], lr1[12];
            LOAD_PAIR6(0, 5, lr0, lr1);
#pragma unroll
            for (int q = 0; q < 8; q++) {
                y1h[q] = __floats2half2_rn(
                    G0 * (zr[q].x + zr[q + 2].x) + G1 * zr[q + 1].x
                  + SH * (Q_E * (lr0[q] + lr0[q + 4]) + Q_D * (lr0[q + 1] + lr0[q + 3]) + Q_F * lr0[q + 2]),
                    G0 * (zr[q].y + zr[q + 2].y) + G1 * zr[q + 1].y
                  + SH * (Q_E * (lr1[q] + lr1[q + 4]) + Q_D * (lr1[q + 1] + lr1[q + 3]) + Q_F * lr1[q + 2]));
            }
        }
        {
            float hl0[12], hl1[12], hh0[12], hh1[12];
            LOAD_PAIR6(2, 3, hl0, hl1);
            LOAD_PAIR6(1, 4, hh0, hh1);
            uint2* o = yp + ((size_t)b * RI + i0) * PS2 + (jp + 2);
#pragma unroll
            for (int q = 0; q < 8; q++) {
                __half2 h2 = __floats2half2_rn(
                    SH * (G0 * (hl0[q + 1] + hl0[q + 3]) + G1 * hl0[q + 2]
                  + Q_E * (hh0[q] + hh0[q + 4]) + Q_D * (hh0[q + 1] + hh0[q + 3]) + Q_F * hh0[q + 2]),
                    SH * (G0 * (hl1[q + 1] + hl1[q + 3]) + G1 * hl1[q + 2]
                  + Q_E * (hh1[q] + hh1[q + 4]) + Q_D * (hh1[q + 1] + hh1[q + 3]) + Q_F * hh1[q + 2]));
                o[q * PS2] = pack2(y1h[q], h2);
            }
        }
#undef LOAD_PAIR6
    } else if (jp < chb) {
#pragma unroll
        for (int dm = 0; dm < 4; dm++) {
            kC_scalar<RI, CI>(z, yh, yp, b, mm + dm, 2 * jp, 2 * jp + 4);
            kC_scalar<RI, CI>(z, yh, yp, b, mm + dm, 2 * jp + 1, 2 * jp + 5);
        }
    } else {
        int hp = jp - chb;
        int pc0 = (hp < 2) ? 2 * hp : (CI + 2 * hp);
#pragma unroll
        for (int dm = 0; dm < 4; dm++) {
#pragma unroll
            for (int s = 0; s < 2; s++) {
                int pc = pc0 + s;
                int jc = refl(pc - 4, CI);
                kC_scalar<RI, CI>(z, yh, yp, b, mm + dm, jc, pc);
            }
        }
    }
}

// ===========================================================================
// kD: branch-free final row filters, 2 rows per thread.
// ===========================================================================
template <int R, int C>
__global__ void __launch_bounds__(256)
kD(const uint2* __restrict__ yp, float* __restrict__ out) {
    constexpr int P = C / 4, PS2 = (C + 10) / 2;
    constexpr int LP = ilog2c(P);
    unsigned idx = blockIdx.x * 256u + threadIdx.x;
    int p = idx & (P - 1);
    int rp = idx >> LP;
    int row0 = 2 * rp;

#pragma unroll
    for (int rr = 0; rr < 2; rr++) {
        int row = row0 + rr;
        const uint2* q = yp + (size_t)row * PS2 + (2 * p + 1);
        uint2 v0 = __ldg(q), v1 = __ldg(q + 1), v2 = __ldg(q + 2), v3 = __ldg(q + 3);
        float2 f0 = unpk_lo(v0), f1 = unpk_lo(v1), f2 = unpk_lo(v2), f3 = unpk_lo(v3);
        float2 g0 = unpk_hi(v0), g1 = unpk_hi(v1), g2 = unpk_hi(v2), g3 = unpk_hi(v3);
        float a[6], v[8];
        a[0] = f0.y; a[1] = f1.x; a[2] = f1.y; a[3] = f2.x; a[4] = f2.y; a[5] = f3.x;
        v[0] = g0.x; v[1] = g0.y; v[2] = g1.x; v[3] = g1.y;
        v[4] = g2.x; v[5] = g2.y; v[6] = g3.x; v[7] = g3.y;
        float4 o;
        o.x = G0 * (a[0] + a[2]) + G1 * a[1] + Q_E * (v[0] + v[4]) + Q_D * (v[1] + v[3]) + Q_F * v[2];
        o.y = G0 * (a[1] + a[3]) + G1 * a[2] + Q_E * (v[1] + v[5]) + Q_D * (v[2] + v[4]) + Q_F * v[3];
        o.z = G0 * (a[2] + a[4]) + G1 * a[3] + Q_E * (v[2] + v[6]) + Q_D * (v[3] + v[5]) + Q_F * v[4];
        o.w = G0 * (a[3] + a[5]) + G1 * a[4] + Q_E * (v[3] + v[7]) + Q_D * (v[4] + v[6]) + Q_F * v[5];
        reinterpret_cast<float4*>(out + (size_t)row * C)[p] = o;
    }
}

extern "C" void kernel_launch(void* const* d_in, const int* in_sizes, int n_in,
                              void* d_out, int out_size) {
    const float *yl = nullptr, *yh0 = nullptr, *yh1 = nullptr, *yh2 = nullptr;
    for (int i = 0; i < n_in; i++) {
        switch (in_sizes[i]) {
            case 524288:   yl  = (const float*)d_in[i]; break;  // 128*64*64
            case 25165824: yh0 = (const float*)d_in[i]; break;  // 128*6*128*128*2
            case 6291456:  yh1 = (const float*)d_in[i]; break;  // 128*6*64*64*2
            case 1572864:  yh2 = (const float*)d_in[i]; break;  // 128*6*32*32*2
            default: break;
        }
    }

    uint2* pyp;
    __half *pz128, *pz256;
    cudaGetSymbolAddress((void**)&pyp,   g_yp);
    cudaGetSymbolAddress((void**)&pz128, g_z128);
    cudaGetSymbolAddress((void**)&pz256, g_z256);

    // Level 1: (64,64) -> (128,128). kA threads: 128 * (rh/4=8) * 37 = 37888
    kA<64, 64, float><<<128 * 8 * 37 / 256, 256>>>(yl, yh2, pyp);
    kB<128, 128><<<128 * 64 * 32 / 256, 256>>>(pyp, pz128);

    // Level 2: (128,128) -> (256,256). kA threads: 128 * 16 * 69 = 141312
    kA<128, 128, __half><<<128 * 16 * 69 / 256, 256>>>(pz128, yh1, pyp);
    kB<256, 256><<<128 * 128 * 64 / 256, 256>>>(pyp, pz256);

    // Final level: kC threads = 128 * 32 * 133
    kC<256, 256><<<128 * 32 * 133 / 256, 256>>>(pz256, yh0, pyp);
    kD<256, 256><<<128 * 128 * 64 / 256, 256>>>(pyp, (float*)d_out);
}

// round 17
// speedup vs baseline: 1.0500x; 1.0500x over previous
#include <cuda_runtime.h>
#include <cuda_fp16.h>

// ---------------------------------------------------------------------------
// Inverse DTCWT, 3 levels. Split kernels, fp16 intermediates, interleaved
// padded y buffer. kA n-PAIR (R14), kC m-QUAD (R15), kB/kD 4 rows/thread.
// ---------------------------------------------------------------------------

#define SH   0.70710678118654752440f
#define C_A  0.23389032f
#define C_B  0.5875183f
#define C_C  0.11430184f
#define C_D  0.76027237f
#define C_E  0.08832942f
#define C_F  0.03516384f

#define G0   0.35355339059327f
#define G1   0.70710678118655f
#define Q_E  (-0.08838834764832f)
#define Q_D  (-0.17677669529664f)
#define Q_F  0.53033008588991f

#define LP0(L) ( C_A*L[1] + C_B*L[2] - C_C*L[3])
#define LP1(L) ( C_D*L[5] - C_E*L[6] + C_F*L[7])
#define LP2(L) ( C_F*L[0] - C_E*L[1] + C_D*L[2])
#define LP3(L) (-C_C*L[4] + C_B*L[5] + C_A*L[6])
#define HP0(H) (-C_D*H[5] + C_E*H[6] - C_F*H[7])
#define HP1(H) ( C_A*H[1] + C_B*H[2] - C_C*H[3])
#define HP2(H) (-C_C*H[4] + C_B*H[5] + C_A*H[6])
#define HP3(H) (-C_F*H[0] + C_E*H[1] - C_D*H[2])

__device__ uint2  g_yp[128 * 256 * 134];
__device__ __half g_z128[128 * 128 * 128];
__device__ __half g_z256[128 * 256 * 256];

__device__ __forceinline__ int refl(int i, int n) {
    i = (i < 0) ? (-1 - i) : i;
    return (i >= n) ? (2 * n - 1 - i) : i;
}

__host__ __device__ constexpr int ilog2c(int v) { return v <= 1 ? 0 : 1 + ilog2c(v >> 1); }

__device__ __forceinline__ float  ld1(const float* p)   { return __ldg(p); }
__device__ __forceinline__ float  ld1(const __half* p)  { return __half2float(__ldg(p)); }
__device__ __forceinline__ float2 ld2(const float2* p)  { return __ldg(p); }
__device__ __forceinline__ float2 ld2(const __half2* p) { return __half22float2(__ldg(p)); }

__device__ __forceinline__ uint2 pack2(__half2 a, __half2 b) {
    uint2 r;
    r.x = *reinterpret_cast<const unsigned*>(&a);
    r.y = *reinterpret_cast<const unsigned*>(&b);
    return r;
}
__device__ __forceinline__ float2 unpk_lo(uint2 v) {
    __half2 h = *reinterpret_cast<const __half2*>(&v.x);
    return __half22float2(h);
}
__device__ __forceinline__ float2 unpk_hi(uint2 v) {
    __half2 h = *reinterpret_cast<const __half2*>(&v.y);
    return __half22float2(h);
}

template <typename T> struct vec2of;
template <> struct vec2of<float>  { using t = float2; };
template <> struct vec2of<__half> { using t = __half2; };

// ===========================================================================
// kA scalar path (single n, single col).
// ===========================================================================
template <int RI, int CI, typename TZ>
__device__ void kA_scalar(const TZ* __restrict__ z, const float* __restrict__ yh,
                          uint2* __restrict__ yp, int b, int n, int jc, int pc) {
    constexpr int rh = RI / 2, PS2 = (CI + 12) / 2;
    const int d8[8] = {-4, -2, 0, 2, -1, 1, 3, 5};
    int pj = jc & 1;
    int rw[8], oB[8];
    float s1v[8], s2v[8];
#pragma unroll
    for (int t = 0; t < 8; t++) {
        int rr = refl(2 * n + d8[t], RI);
        rw[t] = rr;
        int ii = rr >> 1, pi = rr & 1;
        oB[t] = ii * CI + (pi ^ pj);
        s1v[t] = (pi & pj) ? -1.f : 1.f;
        s2v[t] = (pi & (pj ^ 1)) ? -1.f : 1.f;
    }
    const TZ* zb = z + (size_t)b * RI * CI + jc;
    const float* yb = yh + (size_t)b * 6 * rh * CI + 2 * (jc >> 1);
    const int sb = rh * CI;

    float L[8], H[8], A[8], B[8];
#pragma unroll
    for (int t = 0; t < 8; t++) L[t] = ld1(zb + rw[t] * CI);
#pragma unroll
    for (int t = 0; t < 8; t++) {
        H[t] = s1v[t] * __ldg(yb + oB[t]) + s2v[t] * __ldg(yb + 5 * sb + oB[t]);
        A[t] = s1v[t] * __ldg(yb + 2 * sb + oB[t]) + s2v[t] * __ldg(yb + 3 * sb + oB[t]);
        B[t] = s1v[t] * __ldg(yb + 1 * sb + oB[t]) + s2v[t] * __ldg(yb + 4 * sb + oB[t]);
    }

    __half* o = (__half*)yp + (((size_t)b * 2 * RI + 4 * n) * PS2 + (pc >> 1)) * 4 + (pc & 1);
    const int rs = PS2 * 4;
    o[0]          = __float2half(LP0(L) + SH * HP0(H));
    o[2]          = __float2half(SH * (LP0(A) + HP0(B)));
    o[rs]         = __float2half(LP1(L) + SH * HP1(H));
    o[rs + 2]     = __float2half(SH * (LP1(A) + HP1(B)));
    o[2 * rs]     = __float2half(LP2(L) + SH * HP2(H));
    o[2 * rs + 2] = __float2half(SH * (LP2(A) + HP2(B)));
    o[3 * rs]     = __float2half(LP3(L) + SH * HP3(H));
    o[3 * rs + 2] = __float2half(SH * (LP3(A) + HP3(B)));
}

// ===========================================================================
// kA: column upsampling, n-PAIR per thread (R14 verbatim).
// ===========================================================================
template <int RI, int CI, typename TZ>
__global__ void __launch_bounds__(256)
kA(const TZ* __restrict__ z, const float* __restrict__ yh,
   uint2* __restrict__ yp) {
    constexpr int rh = RI / 2, ch = CI / 2, JP = ch + 5, PS2 = (CI + 12) / 2;
    constexpr int NPH = rh / 2;
    using TZ2 = typename vec2of<TZ>::t;
    unsigned idx = blockIdx.x * 256u + threadIdx.x;
    int jp = idx % JP;
    int np = (idx / JP) % NPH;
    int b = idx / (JP * NPH);
    int n = 2 * np;

    if (jp < ch && np >= 1 && np <= NPH - 2) {
        const TZ2* z2 = (const TZ2*)z + (size_t)b * RI * ch + jp;
        const float2* yb2 = (const float2*)yh + (size_t)b * 6 * rh * ch + jp;
        const int sstr = rh * ch;
        int base = 2 * n;

        __half2 y1h[8];
        {
            float2 ze[5], zo[5];
#pragma unroll
            for (int t = 0; t < 5; t++) {
                ze[t] = ld2(z2 + (base - 4 + 2 * t) * ch);
                zo[t] = ld2(z2 + (base - 1 + 2 * t) * ch);
            }
            float E0[5], E1[5], O0[5], O1[5];
            {
                float2 w1[6], w2[6];
#pragma unroll
                for (int t = 0; t < 6; t++) {
                    w1[t] = __ldg(yb2 + (0 * sstr + (n - 2 + t) * ch));
                    w2[t] = __ldg(yb2 + (5 * sstr + (n - 2 + t) * ch));
                }
#pragma unroll
                for (int t = 0; t < 5; t++) {
                    E0[t] = w1[t].x + w2[t].x;
                    E1[t] = w1[t].y + w2[t].y;
                    O0[t] = w1[t + 1].y - w2[t + 1].y;
                    O1[t] = w2[t + 1].x - w1[t + 1].x;
                }
            }
#pragma unroll
            for (int r = 0; r < 2; r++) {
                float L0[8], L1[8], H0[8], H1[8];
#pragma unroll
                for (int t = 0; t < 4; t++) {
                    L0[t] = ze[r + t].x; L1[t] = ze[r + t].y;
                    L0[4 + t] = zo[r + t].x; L1[4 + t] = zo[r + t].y;
                    H0[t] = E0[r + t]; H1[t] = E1[r + t];
                    H0[4 + t] = O0[r + t]; H1[4 + t] = O1[r + t];
                }
                y1h[4 * r + 0] = __floats2half2_rn(LP0(L0) + SH * HP0(H0), LP0(L1) + SH * HP0(H1));
                y1h[4 * r + 1] = __floats2half2_rn(LP1(L0) + SH * HP1(H0), LP1(L1) + SH * HP1(H1));
                y1h[4 * r + 2] = __floats2half2_rn(LP2(L0) + SH * HP2(H0), LP2(L1) + SH * HP2(H1));
                y1h[4 * r + 3] = __floats2half2_rn(LP3(L0) + SH * HP3(H0), LP3(L1) + SH * HP3(H1));
            }
        }

        uint2* o = yp + ((size_t)b * 2 * RI + 4 * n) * PS2 + (jp + 2);
        {
            float AE0[5], AE1[5], AO0[5], AO1[5];
            float BE0[5], BE1[5], BO0[5], BO1[5];
            {
                float2 w1[6], w2[6];
#pragma unroll
                for (int t = 0; t < 6; t++) {
                    w1[t] = __ldg(yb2 + (2 * sstr + (n - 2 + t) * ch));
                    w2[t] = __ldg(yb2 + (3 * sstr + (n - 2 + t) * ch));
                }
#pragma unroll
                for (int t = 0; t < 5; t++) {
                    AE0[t] = w1[t].x + w2[t].x;
                    AE1[t] = w1[t].y + w2[t].y;
                    AO0[t] = w1[t + 1].y - w2[t + 1].y;
                    AO1[t] = w2[t + 1].x - w1[t + 1].x;
                }
            }
            {
                float2 w1[6], w2[6];
#pragma unroll
                for (int t = 0; t < 6; t++) {
                    w1[t] = __ldg(yb2 + (1 * sstr + (n - 2 + t) * ch));
                    w2[t] = __ldg(yb2 + (4 * sstr + (n - 2 + t) * ch));
                }
#pragma unroll
                for (int t = 0; t < 5; t++) {
                    BE0[t] = w1[t].x + w2[t].x;
                    BE1[t] = w1[t].y + w2[t].y;
                    BO0[t] = w1[t + 1].y - w2[t + 1].y;
                    BO1[t] = w2[t + 1].x - w1[t + 1].x;
                }
            }
#pragma unroll
            for (int r = 0; r < 2; r++) {
                float A0[8], A1[8], B0[8], B1[8];
#pragma unroll
                for (int t = 0; t < 4; t++) {
                    A0[t] = AE0[r + t]; A1[t] = AE1[r + t];
                    A0[4 + t] = AO0[r + t]; A1[4 + t] = AO1[r + t];
                    B0[t] = BE0[r + t]; B1[t] = BE1[r + t];
                    B0[4 + t] = BO0[r + t]; B1[4 + t] = BO1[r + t];
                }
                __half2 h0 = __floats2half2_rn(SH * (LP0(A0) + HP0(B0)), SH * (LP0(A1) + HP0(B1)));
                __half2 h1 = __floats2half2_rn(SH * (LP1(A0) + HP1(B0)), SH * (LP1(A1) + HP1(B1)));
                __half2 h2 = __floats2half2_rn(SH * (LP2(A0) + HP2(B0)), SH * (LP2(A1) + HP2(B1)));
                __half2 h3 = __floats2half2_rn(SH * (LP3(A0) + HP3(B0)), SH * (LP3(A1) + HP3(B1)));
                o[(4 * r + 0) * PS2] = pack2(y1h[4 * r + 0], h0);
                o[(4 * r + 1) * PS2] = pack2(y1h[4 * r + 1], h1);
                o[(4 * r + 2) * PS2] = pack2(y1h[4 * r + 2], h2);
                o[(4 * r + 3) * PS2] = pack2(y1h[4 * r + 3], h3);
            }
        }
    } else if (jp < ch) {
#pragma unroll
        for (int dn = 0; dn < 2; dn++) {
            kA_scalar<RI, CI, TZ>(z, yh, yp, b, n + dn, 2 * jp, 2 * jp + 4);
            kA_scalar<RI, CI, TZ>(z, yh, yp, b, n + dn, 2 * jp + 1, 2 * jp + 5);
        }
    } else {
        int hp = jp - ch;
        int pc0 = (hp < 2) ? 2 * hp : (CI + 2 * hp);
#pragma unroll
        for (int dn = 0; dn < 2; dn++) {
#pragma unroll
            for (int s = 0; s < 2; s++) {
                int pc = pc0 + s;
                int jc = refl(pc - 4, CI);
                kA_scalar<RI, CI, TZ>(z, yh, yp, b, n + dn, jc, pc);
            }
        }
    }
}

// ===========================================================================
// kB: branch-free row upsampling, 4 rows per thread.
// ===========================================================================
template <int RO, int CO>
__global__ void __launch_bounds__(256)
kB(const uint2* __restrict__ yp, __half* __restrict__ Z) {
    constexpr int ch = CO / 4;
    constexpr int PS2 = (CO / 2 + 12) / 2;
    constexpr int LCH = ilog2c(ch);
    unsigned idx = blockIdx.x * 256u + threadIdx.x;
    int n = idx & (ch - 1);
    int rp = idx >> LCH;
    int row0 = 4 * rp;

#pragma unroll
    for (int rr = 0; rr < 4; rr++) {
        int row = row0 + rr;
        const uint2* q = yp + (size_t)row * PS2 + n;
        uint2 v0 = __ldg(q), v1 = __ldg(q + 1), v2 = __ldg(q + 2),
              v3 = __ldg(q + 3), v4 = __ldg(q + 4);
        float2 u0 = unpk_lo(v0), u1 = unpk_lo(v1), u2 = unpk_lo(v2),
               u3 = unpk_lo(v3), u4 = unpk_lo(v4);
        float2 w0 = unpk_hi(v0), w1 = unpk_hi(v1), w2 = unpk_hi(v2),
               w3 = unpk_hi(v3), w4 = unpk_hi(v4);
        float L[8], H[8];
        L[0] = u0.x; L[1] = u1.x; L[2] = u2.x; L[3] = u3.x;
        L[4] = u1.y; L[5] = u2.y; L[6] = u3.y; L[7] = u4.y;
        H[0] = w0.x; H[1] = w1.x; H[2] = w2.x; H[3] = w3.x;
        H[4] = w1.y; H[5] = w2.y; H[6] = w3.y; H[7] = w4.y;

        __half2 ha = __floats2half2_rn(LP0(L) + HP0(H), LP1(L) + HP1(H));
        __half2 hb = __floats2half2_rn(LP2(L) + HP2(H), LP3(L) + HP3(H));
        reinterpret_cast<uint2*>(Z + (size_t)row * CO)[n] = pack2(ha, hb);
    }
}

// ===========================================================================
// kC scalar path (single m).
// ===========================================================================
template <int RI, int CI>
__device__ void kC_scalar(const __half* __restrict__ z, const float* __restrict__ yh,
                          uint2* __restrict__ yp, int b, int m, int jc, int pc) {
    constexpr int rh = RI / 2, PS2 = (CI + 10) / 2;
    int i0 = 2 * m;
    int pj = jc & 1;
    int o6[6];
    float s1v[6], s2v[6];
    int rr[6];
#pragma unroll
    for (int t = 0; t < 6; t++) {
        int rx = refl(i0 - 2 + t, RI);
        rr[t] = rx;
        int ii = rx >> 1, pi = rx & 1;
        o6[t] = ii * CI + (pi ^ pj);
        s1v[t] = (pi & pj) ? -1.f : 1.f;
        s2v[t] = (pi & (pj ^ 1)) ? -1.f : 1.f;
    }
    const __half* zb = z + (size_t)b * RI * CI + jc;
    const float* yb = yh + (size_t)b * 6 * rh * CI + 2 * (jc >> 1);
    const int sb = rh * CI;

    float zr[4];
#pragma unroll
    for (int t = 0; t < 4; t++) zr[t] = ld1(zb + rr[t + 1] * CI);

    float lr[6], hlr[6], hhr[6];
#pragma unroll
    for (int t = 0; t < 6; t++) {
        lr[t]  = s1v[t] * __ldg(yb + o6[t])          + s2v[t] * __ldg(yb + 5 * sb + o6[t]);
        hlr[t] = s1v[t] * __ldg(yb + 2 * sb + o6[t]) + s2v[t] * __ldg(yb + 3 * sb + o6[t]);
        hhr[t] = s1v[t] * __ldg(yb + 1 * sb + o6[t]) + s2v[t] * __ldg(yb + 4 * sb + o6[t]);
    }
    __half* o = (__half*)yp + (((size_t)b * RI + i0) * PS2 + (pc >> 1)) * 4 + (pc & 1);
    const int rs = PS2 * 4;
    o[0]      = __float2half(G0 * (zr[0] + zr[2]) + G1 * zr[1]
              + SH * (Q_E * (lr[0] + lr[4]) + Q_D * (lr[1] + lr[3]) + Q_F * lr[2]));
    o[rs]     = __float2half(G0 * (zr[1] + zr[3]) + G1 * zr[2]
              + SH * (Q_E * (lr[1] + lr[5]) + Q_D * (lr[2] + lr[4]) + Q_F * lr[3]));
    o[2]      = __float2half(SH * (G0 * (hlr[1] + hlr[3]) + G1 * hlr[2]
              + Q_E * (hhr[0] + hhr[4]) + Q_D * (hhr[1] + hhr[3]) + Q_F * hhr[2]));
    o[rs + 2] = __float2half(SH * (G0 * (hlr[2] + hlr[4]) + G1 * hlr[3]
              + Q_E * (hhr[1] + hhr[5]) + Q_D * (hhr[2] + hhr[4]) + Q_F * hhr[3]));
}

// ===========================================================================
// kC: final-level column filters, m-QUAD per thread, two-pass (R15 verbatim).
// ===========================================================================
template <int RI, int CI>
__global__ void __launch_bounds__(256)
kC(const __half* __restrict__ z, const float* __restrict__ yh,
   uint2* __restrict__ yp) {
    constexpr int rh = RI / 2, chb = CI / 2, JP = chb + 5, PS2 = (CI + 10) / 2;
    constexpr int MQ = rh / 4;
    unsigned idx = blockIdx.x * 256u + threadIdx.x;
    int jp = idx % JP;
    int mq = (idx / JP) % MQ;
    int b = idx / (JP * MQ);
    int mm = 4 * mq;
    int i0 = 2 * mm;

    if (jp < chb && mq >= 1 && mq <= MQ - 2) {
        const __half2* z2 = (const __half2*)z + (size_t)b * RI * chb + jp;
        const float2* yb2 = (const float2*)yh + (size_t)b * 6 * rh * chb + jp;
        const int sstr = rh * chb;

#define LOAD_PAIR6(S1, S2, B0, B1)                                            \
    {                                                                         \
        float2 w1[6], w2[6];                                                  \
        _Pragma("unroll") for (int t = 0; t < 6; t++) {                       \
            w1[t] = __ldg(yb2 + ((S1) * sstr + (mm - 1 + t) * chb));          \
            w2[t] = __ldg(yb2 + ((S2) * sstr + (mm - 1 + t) * chb));          \
        }                                                                     \
        _Pragma("unroll") for (int t = 0; t < 6; t++) {                       \
            B0[2 * t] = w1[t].x + w2[t].x;                                    \
            B1[2 * t] = w1[t].y + w2[t].y;                                    \
            B0[2 * t + 1] = w1[t].y - w2[t].y;                                \
            B1[2 * t + 1] = w2[t].x - w1[t].x;                                \
        }                                                                     \
    }

        __half2 y1h[8];
        {
            float2 zr[10];
#pragma unroll
            for (int t = 0; t < 10; t++) zr[t] = ld2(z2 + (i0 - 1 + t) * chb);
            float lr0[12], lr1[12];
            LOAD_PAIR6(0, 5, lr0, lr1);
#pragma unroll
            for (int q = 0; q < 8; q++) {
                y1h[q] = __floats2half2_rn(
                    G0 * (zr[q].x + zr[q + 2].x) + G1 * zr[q + 1].x
                  + SH * (Q_E * (lr0[q] + lr0[q + 4]) + Q_D * (lr0[q + 1] + lr0[q + 3]) + Q_F * lr0[q + 2]),
                    G0 * (zr[q].y + zr[q + 2].y) + G1 * zr[q + 1].y
                  + SH * (Q_E * (lr1[q] + lr1[q + 4]) + Q_D * (lr1[q + 1] + lr1[q + 3]) + Q_F * lr1[q + 2]));
            }
        }
        {
            float hl0[12], hl1[12], hh0[12], hh1[12];
            LOAD_PAIR6(2, 3, hl0, hl1);
            LOAD_PAIR6(1, 4, hh0, hh1);
            uint2* o = yp + ((size_t)b * RI + i0) * PS2 + (jp + 2);
#pragma unroll
            for (int q = 0; q < 8; q++) {
                __half2 h2 = __floats2half2_rn(
                    SH * (G0 * (hl0[q + 1] + hl0[q + 3]) + G1 * hl0[q + 2]
                  + Q_E * (hh0[q] + hh0[q + 4]) + Q_D * (hh0[q + 1] + hh0[q + 3]) + Q_F * hh0[q + 2]),
                    SH * (G0 * (hl1[q + 1] + hl1[q + 3]) + G1 * hl1[q + 2]
                  + Q_E * (hh1[q] + hh1[q + 4]) + Q_D * (hh1[q + 1] + hh1[q + 3]) + Q_F * hh1[q + 2]));
                o[q * PS2] = pack2(y1h[q], h2);
            }
        }
#undef LOAD_PAIR6
    } else if (jp < chb) {
#pragma unroll
        for (int dm = 0; dm < 4; dm++) {
            kC_scalar<RI, CI>(z, yh, yp, b, mm + dm, 2 * jp, 2 * jp + 4);
            kC_scalar<RI, CI>(z, yh, yp, b, mm + dm, 2 * jp + 1, 2 * jp + 5);
        }
    } else {
        int hp = jp - chb;
        int pc0 = (hp < 2) ? 2 * hp : (CI + 2 * hp);
#pragma unroll
        for (int dm = 0; dm < 4; dm++) {
#pragma unroll
            for (int s = 0; s < 2; s++) {
                int pc = pc0 + s;
                int jc = refl(pc - 4, CI);
                kC_scalar<RI, CI>(z, yh, yp, b, mm + dm, jc, pc);
            }
        }
    }
}

// ===========================================================================
// kD: branch-free final row filters, 4 rows per thread.
// ===========================================================================
template <int R, int C>
__global__ void __launch_bounds__(256)
kD(const uint2* __restrict__ yp, float* __restrict__ out) {
    constexpr int P = C / 4, PS2 = (C + 10) / 2;
    constexpr int LP = ilog2c(P);
    unsigned idx = blockIdx.x * 256u + threadIdx.x;
    int p = idx & (P - 1);
    int rp = idx >> LP;
    int row0 = 4 * rp;

#pragma unroll
    for (int rr = 0; rr < 4; rr++) {
        int row = row0 + rr;
        const uint2* q = yp + (size_t)row * PS2 + (2 * p + 1);
        uint2 v0 = __ldg(q), v1 = __ldg(q + 1), v2 = __ldg(q + 2), v3 = __ldg(q + 3);
        float2 f0 = unpk_lo(v0), f1 = unpk_lo(v1), f2 = unpk_lo(v2), f3 = unpk_lo(v3);
        float2 g0 = unpk_hi(v0), g1 = unpk_hi(v1), g2 = unpk_hi(v2), g3 = unpk_hi(v3);
        float a[6], v[8];
        a[0] = f0.y; a[1] = f1.x; a[2] = f1.y; a[3] = f2.x; a[4] = f2.y; a[5] = f3.x;
        v[0] = g0.x; v[1] = g0.y; v[2] = g1.x; v[3] = g1.y;
        v[4] = g2.x; v[5] = g2.y; v[6] = g3.x; v[7] = g3.y;
        float4 o;
        o.x = G0 * (a[0] + a[2]) + G1 * a[1] + Q_E * (v[0] + v[4]) + Q_D * (v[1] + v[3]) + Q_F * v[2];
        o.y = G0 * (a[1] + a[3]) + G1 * a[2] + Q_E * (v[1] + v[5]) + Q_D * (v[2] + v[4]) + Q_F * v[3];
        o.z = G0 * (a[2] + a[4]) + G1 * a[3] + Q_E * (v[2] + v[6]) + Q_D * (v[3] + v[5]) + Q_F * v[4];
        o.w = G0 * (a[3] + a[5]) + G1 * a[4] + Q_E * (v[3] + v[7]) + Q_D * (v[4] + v[6]) + Q_F * v[5];
        reinterpret_cast<float4*>(out + (size_t)row * C)[p] = o;
    }
}

extern "C" void kernel_launch(void* const* d_in, const int* in_sizes, int n_in,
                              void* d_out, int out_size) {
    const float *yl = nullptr, *yh0 = nullptr, *yh1 = nullptr, *yh2 = nullptr;
    for (int i = 0; i < n_in; i++) {
        switch (in_sizes[i]) {
            case 524288:   yl  = (const float*)d_in[i]; break;  // 128*64*64
            case 25165824: yh0 = (const float*)d_in[i]; break;  // 128*6*128*128*2
            case 6291456:  yh1 = (const float*)d_in[i]; break;  // 128*6*64*64*2
            case 1572864:  yh2 = (const float*)d_in[i]; break;  // 128*6*32*32*2
            default: break;
        }
    }

    uint2* pyp;
    __half *pz128, *pz256;
    cudaGetSymbolAddress((void**)&pyp,   g_yp);
    cudaGetSymbolAddress((void**)&pz128, g_z128);
    cudaGetSymbolAddress((void**)&pz256, g_z256);

    // Level 1: (64,64) -> (128,128)
    kA<64, 64, float><<<128 * 16 * 37 / 256, 256>>>(yl, yh2, pyp);
    kB<128, 128><<<128 * 32 * 32 / 256, 256>>>(pyp, pz128);

    // Level 2: (128,128) -> (256,256)
    kA<128, 128, __half><<<128 * 32 * 69 / 256, 256>>>(pz128, yh1, pyp);
    kB<256, 256><<<128 * 64 * 64 / 256, 256>>>(pyp, pz256);

    // Final level
    kC<256, 256><<<128 * 32 * 133 / 256, 256>>>(pz256, yh0, pyp);
    kD<256, 256><<<128 * 64 * 64 / 256, 256>>>(pyp, (float*)d_out);
}